// round 2
// baseline (speedup 1.0000x reference)
#include <cuda_runtime.h>
#include <cuda_bf16.h>
#include <cstdint>

// ---------------- problem constants ----------------
#define NEXP 64
#define DIM  2048
#define HID  1024
#define TOK  16384
#define TPE  256

// 64 MB scratch for the SwiGLU intermediate h [TOK, HID] fp32
__device__ float g_h[(size_t)TOK * HID];

// ---------------- helpers ----------------
__device__ __forceinline__ uint32_t smem_u32(const void* p) {
    uint32_t a;
    asm("{ .reg .u64 t; cvta.to.shared.u64 t, %1; cvt.u32.u64 %0, t; }" : "=r"(a) : "l"(p));
    return a;
}
// round-to-nearest tf32 conversion (unbiased; critical for 1e-3 tolerance)
__device__ __forceinline__ uint32_t f2tf32(float x) {
    uint32_t r;
    asm("cvt.rna.tf32.f32 %0, %1;" : "=r"(r) : "f"(x));
    return r;
}

#define SWZ(x) ((x) ^ (((x) >> 3) & 0x70))

// ldmatrix x4: loads four 8x4 tf32 blocks (each 8 rows x 16B)
__device__ __forceinline__ void ldsm4(uint32_t* f, uint32_t addr) {
    asm volatile("ldmatrix.sync.aligned.m8n8.x4.shared.b16 {%0,%1,%2,%3}, [%4];"
                 : "=r"(f[0]), "=r"(f[1]), "=r"(f[2]), "=r"(f[3]) : "r"(addr));
}

// mma m16n8k8 tf32, D += A*B
__device__ __forceinline__ void mma8(float* d, const uint32_t* a, uint32_t b0, uint32_t b1) {
    asm volatile("mma.sync.aligned.m16n8k8.row.col.f32.tf32.tf32.f32 "
                 "{%0,%1,%2,%3},{%4,%5,%6,%7},{%8,%9},{%0,%1,%2,%3};"
                 : "+f"(d[0]), "+f"(d[1]), "+f"(d[2]), "+f"(d[3])
                 : "r"(a[0]), "r"(a[1]), "r"(a[2]), "r"(a[3]), "r"(b0), "r"(b1));
}

__device__ __forceinline__ float silu(float v) {
    return v / (1.0f + __expf(-v));
}

#define UP_STAGE 32768   // A 16KB + W1 8KB + W3 8KB
#define DN_STAGE 32768   // A 16KB + W2 16KB
#define SMEM_TOTAL (2 * 32768)

// ======================================================================
// Kernel A: h = silu(X@W1) * (X@W3) per expert
// CTA tile: 128 m x 64 n (both W1 and W3). grid = 64 * 2 * 16 = 2048 CTAs.
// 8 warps arranged 4m x 2n; warp tile 32m x 32n per GEMM.
// ======================================================================
__global__ __launch_bounds__(256, 1)
void moe_up_kernel(const float* __restrict__ x,
                   const float* __restrict__ w1,
                   const float* __restrict__ w3)
{
    extern __shared__ __align__(1024) char smem[];
    const int tid  = threadIdx.x;
    const int lane = tid & 31;
    const int wid  = tid >> 5;
    const int bid  = blockIdx.x;
    const int e    = bid >> 5;
    const int rem  = bid & 31;
    const int mt   = rem & 1;      // token tile (0..1)
    const int nt   = rem >> 1;     // hidden tile (0..15), 64 wide

    const float* xb  = x  + (size_t)(e * TPE + mt * 128) * DIM;
    const float* w1b = w1 + (size_t)e * DIM * HID + nt * 64;
    const float* w3b = w3 + (size_t)e * DIM * HID + nt * 64;

    const int wm = wid >> 1, wn = wid & 1;
    const int mbase = wm * 32, nbase = wn * 32;
    const int blk = lane >> 3, r = lane & 7;

    // staging register indices
    const int am = tid >> 3, aq = tid & 7;      // A: rows am + j*32, 16B chunk aq
    const int bn = tid & 63, bkq0 = tid >> 6;   // B: row bn, chunk bkq0 + j*4

    uint4 sA[4], sB1[2], sB3[2];

    auto ldg = [&](int k0) {
        #pragma unroll
        for (int j = 0; j < 4; j++) {
            float4 v = *(const float4*)(xb + (size_t)(am + j * 32) * DIM + k0 + aq * 4);
            sA[j] = make_uint4(f2tf32(v.x), f2tf32(v.y), f2tf32(v.z), f2tf32(v.w));
        }
        #pragma unroll
        for (int j = 0; j < 2; j++) {
            int kq = bkq0 + j * 4;
            const float* p1 = w1b + (size_t)(k0 + kq * 4) * HID + bn;
            sB1[j] = make_uint4(f2tf32(p1[0]), f2tf32(p1[HID]), f2tf32(p1[2 * HID]), f2tf32(p1[3 * HID]));
            const float* p3 = w3b + (size_t)(k0 + kq * 4) * HID + bn;
            sB3[j] = make_uint4(f2tf32(p3[0]), f2tf32(p3[HID]), f2tf32(p3[2 * HID]), f2tf32(p3[3 * HID]));
        }
    };
    auto sts = [&](char* buf) {
        #pragma unroll
        for (int j = 0; j < 4; j++)
            *(uint4*)(buf + SWZ((am + j * 32) * 128 + aq * 16)) = sA[j];
        #pragma unroll
        for (int j = 0; j < 2; j++) {
            int kq = bkq0 + j * 4;
            *(uint4*)(buf + 16384 + SWZ(bn * 128 + kq * 16)) = sB1[j];
            *(uint4*)(buf + 24576 + SWZ(bn * 128 + kq * 16)) = sB3[j];
        }
    };

    float acc1[2][4][4], acc3[2][4][4];
    #pragma unroll
    for (int i = 0; i < 2; i++)
        #pragma unroll
        for (int j = 0; j < 4; j++)
            #pragma unroll
            for (int k = 0; k < 4; k++) { acc1[i][j][k] = 0.f; acc3[i][j][k] = 0.f; }

    const uint32_t sbase = smem_u32(smem);

    ldg(0);
    sts(smem);
    __syncthreads();

    const int NS = DIM / 32;   // 64 stages
    #pragma unroll 1
    for (int s = 0; s < NS; s++) {
        if (s + 1 < NS) ldg((s + 1) * 32);
        const uint32_t aA  = sbase + (uint32_t)(s & 1) * UP_STAGE;
        const uint32_t aB1 = aA + 16384;
        const uint32_t aB3 = aA + 24576;
        #pragma unroll
        for (int kk = 0; kk < 4; kk++) {
            uint32_t af[2][4];
            #pragma unroll
            for (int m2 = 0; m2 < 2; m2++)
                ldsm4(af[m2], aA + SWZ((mbase + m2 * 16 + (blk & 1) * 8 + r) * 128 + kk * 32 + (blk >> 1) * 16));
            #pragma unroll
            for (int p = 0; p < 2; p++) {
                uint32_t off = SWZ((nbase + p * 16 + (blk >> 1) * 8 + r) * 128 + kk * 32 + (blk & 1) * 16);
                uint32_t bf1[4], bf3[4];
                ldsm4(bf1, aB1 + off);
                ldsm4(bf3, aB3 + off);
                #pragma unroll
                for (int m2 = 0; m2 < 2; m2++) {
                    mma8(acc1[m2][p * 2 + 0], af[m2], bf1[0], bf1[1]);
                    mma8(acc1[m2][p * 2 + 1], af[m2], bf1[2], bf1[3]);
                    mma8(acc3[m2][p * 2 + 0], af[m2], bf3[0], bf3[1]);
                    mma8(acc3[m2][p * 2 + 1], af[m2], bf3[2], bf3[3]);
                }
            }
        }
        if (s + 1 < NS) sts(smem + ((s + 1) & 1) * UP_STAGE);
        __syncthreads();
    }

    // fused SwiGLU epilogue -> g_h
    const int g = lane >> 2, t4 = lane & 3;
    float* hb = g_h + (size_t)(e * TPE + mt * 128) * HID + nt * 64;
    #pragma unroll
    for (int m2 = 0; m2 < 2; m2++) {
        #pragma unroll
        for (int n8 = 0; n8 < 4; n8++) {
            int col = nbase + n8 * 8 + 2 * t4;
            float* row0 = hb + (size_t)(mbase + m2 * 16 + g) * HID + col;
            float* row1 = row0 + 8 * HID;
            float v0 = silu(acc1[m2][n8][0]) * acc3[m2][n8][0];
            float v1 = silu(acc1[m2][n8][1]) * acc3[m2][n8][1];
            float v2 = silu(acc1[m2][n8][2]) * acc3[m2][n8][2];
            float v3 = silu(acc1[m2][n8][3]) * acc3[m2][n8][3];
            *(float2*)row0 = make_float2(v0, v1);
            *(float2*)row1 = make_float2(v2, v3);
        }
    }
}

// ======================================================================
// Kernel B: out = h @ W2 per expert
// CTA tile: 128 m x 128 n. grid = 64 * 2 * 16 = 2048 CTAs.
// 8 warps 4m x 2n; warp tile 32m x 64n.
// ======================================================================
__global__ __launch_bounds__(256, 1)
void moe_down_kernel(const float* __restrict__ w2, float* __restrict__ out)
{
    extern __shared__ __align__(1024) char smem[];
    const int tid  = threadIdx.x;
    const int lane = tid & 31;
    const int wid  = tid >> 5;
    const int bid  = blockIdx.x;
    const int e    = bid >> 5;
    const int rem  = bid & 31;
    const int mt   = rem & 1;      // token tile
    const int nt   = rem >> 1;     // dim tile (0..15), 128 wide

    const float* hb  = g_h + (size_t)(e * TPE + mt * 128) * HID;
    const float* w2b = w2 + (size_t)e * HID * DIM + nt * 128;

    const int wm = wid >> 1, wn = wid & 1;
    const int mbase = wm * 32, nbase = wn * 64;
    const int blk = lane >> 3, r = lane & 7;

    const int am = tid >> 3, aq = tid & 7;
    const int bn = tid & 127, bkq0 = tid >> 7;   // chunk bkq0 + j*2

    uint4 sA[4], sB[4];

    auto ldg = [&](int k0) {
        #pragma unroll
        for (int j = 0; j < 4; j++) {
            float4 v = *(const float4*)(hb + (size_t)(am + j * 32) * HID + k0 + aq * 4);
            sA[j] = make_uint4(f2tf32(v.x), f2tf32(v.y), f2tf32(v.z), f2tf32(v.w));
        }
        #pragma unroll
        for (int j = 0; j < 4; j++) {
            int kq = bkq0 + j * 2;
            const float* p = w2b + (size_t)(k0 + kq * 4) * DIM + bn;
            sB[j] = make_uint4(f2tf32(p[0]), f2tf32(p[DIM]), f2tf32(p[2 * DIM]), f2tf32(p[3 * DIM]));
        }
    };
    auto sts = [&](char* buf) {
        #pragma unroll
        for (int j = 0; j < 4; j++)
            *(uint4*)(buf + SWZ((am + j * 32) * 128 + aq * 16)) = sA[j];
        #pragma unroll
        for (int j = 0; j < 4; j++) {
            int kq = bkq0 + j * 2;
            *(uint4*)(buf + 16384 + SWZ(bn * 128 + kq * 16)) = sB[j];
        }
    };

    float acc[2][8][4];
    #pragma unroll
    for (int i = 0; i < 2; i++)
        #pragma unroll
        for (int j = 0; j < 8; j++)
            #pragma unroll
            for (int k = 0; k < 4; k++) acc[i][j][k] = 0.f;

    const uint32_t sbase = smem_u32(smem);

    ldg(0);
    sts(smem);
    __syncthreads();

    const int NS = HID / 32;   // 32 stages
    #pragma unroll 1
    for (int s = 0; s < NS; s++) {
        if (s + 1 < NS) ldg((s + 1) * 32);
        const uint32_t aA = sbase + (uint32_t)(s & 1) * DN_STAGE;
        const uint32_t aB = aA + 16384;
        #pragma unroll
        for (int kk = 0; kk < 4; kk++) {
            uint32_t af[2][4];
            #pragma unroll
            for (int m2 = 0; m2 < 2; m2++)
                ldsm4(af[m2], aA + SWZ((mbase + m2 * 16 + (blk & 1) * 8 + r) * 128 + kk * 32 + (blk >> 1) * 16));
            #pragma unroll
            for (int p = 0; p < 4; p++) {
                uint32_t off = SWZ((nbase + p * 16 + (blk >> 1) * 8 + r) * 128 + kk * 32 + (blk & 1) * 16);
                uint32_t bf[4];
                ldsm4(bf, aB + off);
                #pragma unroll
                for (int m2 = 0; m2 < 2; m2++) {
                    mma8(acc[m2][p * 2 + 0], af[m2], bf[0], bf[1]);
                    mma8(acc[m2][p * 2 + 1], af[m2], bf[2], bf[3]);
                }
            }
        }
        if (s + 1 < NS) sts(smem + ((s + 1) & 1) * DN_STAGE);
        __syncthreads();
    }

    const int g = lane >> 2, t4 = lane & 3;
    float* ob = out + (size_t)(e * TPE + mt * 128) * DIM + nt * 128;
    #pragma unroll
    for (int m2 = 0; m2 < 2; m2++) {
        #pragma unroll
        for (int n8 = 0; n8 < 8; n8++) {
            int col = nbase + n8 * 8 + 2 * t4;
            float* row0 = ob + (size_t)(mbase + m2 * 16 + g) * DIM + col;
            float* row1 = row0 + 8 * DIM;
            *(float2*)row0 = make_float2(acc[m2][n8][0], acc[m2][n8][1]);
            *(float2*)row1 = make_float2(acc[m2][n8][2], acc[m2][n8][3]);
        }
    }
}

// ======================================================================
extern "C" void kernel_launch(void* const* d_in, const int* in_sizes, int n_in,
                              void* d_out, int out_size)
{
    (void)in_sizes; (void)n_in; (void)out_size;
    const float* x  = (const float*)d_in[0];
    const float* w1 = (const float*)d_in[1];
    const float* w2 = (const float*)d_in[2];
    const float* w3 = (const float*)d_in[3];
    float* out = (float*)d_out;

    static bool attr_set = false;
    if (!attr_set) {
        cudaFuncSetAttribute(moe_up_kernel,   cudaFuncAttributeMaxDynamicSharedMemorySize, SMEM_TOTAL);
        cudaFuncSetAttribute(moe_down_kernel, cudaFuncAttributeMaxDynamicSharedMemorySize, SMEM_TOTAL);
        attr_set = true;
    }

    moe_up_kernel<<<NEXP * 32, 256, SMEM_TOTAL>>>(x, w1, w3);
    moe_down_kernel<<<NEXP * 32, 256, SMEM_TOTAL>>>(w2, out);
}

// round 3
// speedup vs baseline: 1.8016x; 1.8016x over previous
#include <cuda_runtime.h>
#include <cuda_bf16.h>
#include <cstdint>

// ---------------- problem constants ----------------
#define NEXP 64
#define DIM  2048
#define HID  1024
#define TOK  16384
#define TPE  256

// 64 MB scratch for the SwiGLU intermediate h [TOK, HID] fp32
__device__ float g_h[(size_t)TOK * HID];

// ---------------- helpers ----------------
__device__ __forceinline__ uint32_t smem_u32(const void* p) {
    uint32_t a;
    asm("{ .reg .u64 t; cvta.to.shared.u64 t, %1; cvt.u32.u64 %0, t; }" : "=r"(a) : "l"(p));
    return a;
}
// round-to-nearest tf32 conversion (unbiased; critical for 1e-3 tolerance)
__device__ __forceinline__ uint32_t f2tf32(float x) {
    uint32_t r;
    asm("cvt.rna.tf32.f32 %0, %1;" : "=r"(r) : "f"(x));
    return r;
}
__device__ __forceinline__ uint32_t bits2tf32(uint32_t b) {
    return f2tf32(__uint_as_float(b));
}

#define SWZ(x) ((x) ^ (((x) >> 3) & 0x70))

__device__ __forceinline__ void cp16(uint32_t dst, const void* src) {
    asm volatile("cp.async.cg.shared.global [%0], [%1], 16;" :: "r"(dst), "l"(src));
}
#define CP_COMMIT() asm volatile("cp.async.commit_group;" ::: "memory")
#define CP_WAIT1()  asm volatile("cp.async.wait_group 1;" ::: "memory")

// ldmatrix x4: loads four 8x4 tf32 blocks (each 8 rows x 16B)
__device__ __forceinline__ void ldsm4(uint32_t* f, uint32_t addr) {
    asm volatile("ldmatrix.sync.aligned.m8n8.x4.shared.b16 {%0,%1,%2,%3}, [%4];"
                 : "=r"(f[0]), "=r"(f[1]), "=r"(f[2]), "=r"(f[3]) : "r"(addr));
}

// mma m16n8k8 tf32, D += A*B
__device__ __forceinline__ void mma8(float* d, const uint32_t* a, uint32_t b0, uint32_t b1) {
    asm volatile("mma.sync.aligned.m16n8k8.row.col.f32.tf32.tf32.f32 "
                 "{%0,%1,%2,%3},{%4,%5,%6,%7},{%8,%9},{%0,%1,%2,%3};"
                 : "+f"(d[0]), "+f"(d[1]), "+f"(d[2]), "+f"(d[3])
                 : "r"(a[0]), "r"(a[1]), "r"(a[2]), "r"(a[3]), "r"(b0), "r"(b1));
}

__device__ __forceinline__ float silu(float v) {
    return v / (1.0f + __expf(-v));
}

// ---------------- smem layout ----------------
// DOWN: A[m128,k32] SW128 16384B + B[k32][n128] rows padded to 544B (136 floats) = 17408B
#define DN_BROW   136
#define DN_STAGE  33792
#define DN_SMEM   (3 * DN_STAGE)       // 101376
// UP: A 16384B + B1[k32][n64] rows padded to 288B (72 floats) 9216B + B3 9216B
#define UP_BROW   72
#define UP_B1OFF  16384
#define UP_B3OFF  25600
#define UP_STAGE  34816
#define UP_SMEM   (3 * UP_STAGE)       // 104448

// ======================================================================
// Kernel A: h = silu(X@W1) * (X@W3) per expert
// CTA: 128m x 64n (both W1,W3). 8 warps 2m x 4n; warp tile 64m x 16n per GEMM.
// grid = 64 * 2 * 16 = 2048
// ======================================================================
__global__ __launch_bounds__(256, 2)
void moe_up_kernel(const float* __restrict__ x,
                   const float* __restrict__ w1,
                   const float* __restrict__ w3)
{
    extern __shared__ __align__(1024) char smem[];
    const uint32_t sbase = smem_u32(smem);
    const int tid  = threadIdx.x;
    const int lane = tid & 31;
    const int wid  = tid >> 5;
    const int bid  = blockIdx.x;
    const int e    = bid >> 5;
    const int rem  = bid & 31;
    const int mt   = rem & 1;
    const int nt   = rem >> 1;       // 16 tiles of 64

    const float* xb  = x  + (size_t)(e * TPE + mt * 128) * DIM;
    const float* w1b = w1 + (size_t)e * DIM * HID + nt * 64;
    const float* w3b = w3 + (size_t)e * DIM * HID + nt * 64;

    const int wm = wid >> 2, wn = wid & 3;
    const int mbase = wm * 64, nbase = wn * 16;
    const int blk = lane >> 3, r = lane & 7;

    // loader indices
    const int am = tid >> 3, aq = tid & 7;   // A: rows am + j*32, chunk aq
    const int bk = tid >> 4, bq = tid & 15;  // B: rows bk + j*16, chunk bq

    auto issue = [&](int s) {
        const uint32_t buf = sbase + (uint32_t)(s % 3) * UP_STAGE;
        const int k0 = s * 32;
        #pragma unroll
        for (int j = 0; j < 4; j++) {
            int m = am + j * 32;
            cp16(buf + SWZ(m * 128 + aq * 16), xb + (size_t)m * DIM + k0 + aq * 4);
        }
        #pragma unroll
        for (int j = 0; j < 2; j++) {
            int k = bk + j * 16;
            cp16(buf + UP_B1OFF + k * 288 + bq * 16, w1b + (size_t)(k0 + k) * HID + bq * 4);
            cp16(buf + UP_B3OFF + k * 288 + bq * 16, w3b + (size_t)(k0 + k) * HID + bq * 4);
        }
    };

    float acc1[4][2][4], acc3[4][2][4];
    #pragma unroll
    for (int i = 0; i < 4; i++)
        #pragma unroll
        for (int j = 0; j < 2; j++)
            #pragma unroll
            for (int k = 0; k < 4; k++) { acc1[i][j][k] = 0.f; acc3[i][j][k] = 0.f; }

    issue(0); CP_COMMIT();
    issue(1); CP_COMMIT();

    const int kb = lane & 3, nq = lane >> 2;
    const int NS = DIM / 32;   // 64
    #pragma unroll 1
    for (int s = 0; s < NS; s++) {
        CP_WAIT1();
        __syncthreads();
        const uint32_t aA = sbase + (uint32_t)(s % 3) * UP_STAGE;
        const float* B1p = (const float*)(smem + (s % 3) * UP_STAGE + UP_B1OFF);
        const float* B3p = (const float*)(smem + (s % 3) * UP_STAGE + UP_B3OFF);
        #pragma unroll
        for (int kk = 0; kk < 4; kk++) {
            uint32_t af[4][4];
            #pragma unroll
            for (int m2 = 0; m2 < 4; m2++) {
                ldsm4(af[m2], aA + SWZ((mbase + m2 * 16 + (blk & 1) * 8 + r) * 128 + kk * 32 + (blk >> 1) * 16));
                #pragma unroll
                for (int q = 0; q < 4; q++) af[m2][q] = bits2tf32(af[m2][q]);
            }
            uint32_t b10[2], b11[2], b30[2], b31[2];
            #pragma unroll
            for (int p = 0; p < 2; p++) {
                int n = nbase + p * 8 + nq;
                int k = kk * 8 + kb;
                b10[p] = f2tf32(B1p[k * UP_BROW + n]);
                b11[p] = f2tf32(B1p[(k + 4) * UP_BROW + n]);
                b30[p] = f2tf32(B3p[k * UP_BROW + n]);
                b31[p] = f2tf32(B3p[(k + 4) * UP_BROW + n]);
            }
            #pragma unroll
            for (int m2 = 0; m2 < 4; m2++)
                #pragma unroll
                for (int p = 0; p < 2; p++) {
                    mma8(acc1[m2][p], af[m2], b10[p], b11[p]);
                    mma8(acc3[m2][p], af[m2], b30[p], b31[p]);
                }
        }
        if (s + 2 < NS) issue(s + 2);
        CP_COMMIT();
    }

    // fused SwiGLU epilogue -> g_h
    const int g = lane >> 2, t4 = lane & 3;
    float* hb = g_h + (size_t)(e * TPE + mt * 128) * HID + nt * 64;
    #pragma unroll
    for (int m2 = 0; m2 < 4; m2++) {
        #pragma unroll
        for (int p = 0; p < 2; p++) {
            int row = mbase + m2 * 16 + g;
            int col = nbase + p * 8 + 2 * t4;
            float* r0 = hb + (size_t)row * HID + col;
            float* r1 = r0 + 8 * HID;
            *(float2*)r0 = make_float2(silu(acc1[m2][p][0]) * acc3[m2][p][0],
                                       silu(acc1[m2][p][1]) * acc3[m2][p][1]);
            *(float2*)r1 = make_float2(silu(acc1[m2][p][2]) * acc3[m2][p][2],
                                       silu(acc1[m2][p][3]) * acc3[m2][p][3]);
        }
    }
}

// ======================================================================
// Kernel B: out = h @ W2 per expert
// CTA: 128m x 128n. 8 warps 2m x 4n; warp tile 64m x 32n.
// grid = 64 * 2 * 16 = 2048
// ======================================================================
__global__ __launch_bounds__(256, 2)
void moe_down_kernel(const float* __restrict__ w2, float* __restrict__ out)
{
    extern __shared__ __align__(1024) char smem[];
    const uint32_t sbase = smem_u32(smem);
    const int tid  = threadIdx.x;
    const int lane = tid & 31;
    const int wid  = tid >> 5;
    const int bid  = blockIdx.x;
    const int e    = bid >> 5;
    const int rem  = bid & 31;
    const int mt   = rem & 1;
    const int nt   = rem >> 1;       // 16 tiles of 128

    const float* hb  = g_h + (size_t)(e * TPE + mt * 128) * HID;
    const float* w2b = w2 + (size_t)e * HID * DIM + nt * 128;

    const int wm = wid >> 2, wn = wid & 3;
    const int mbase = wm * 64, nbase = wn * 32;
    const int blk = lane >> 3, r = lane & 7;

    const int am = tid >> 3, aq = tid & 7;   // A rows am + j*32
    const int bk = tid >> 5, bq = tid & 31;  // B rows bk + j*8, chunk bq

    auto issue = [&](int s) {
        const uint32_t buf = sbase + (uint32_t)(s % 3) * DN_STAGE;
        const int k0 = s * 32;
        #pragma unroll
        for (int j = 0; j < 4; j++) {
            int m = am + j * 32;
            cp16(buf + SWZ(m * 128 + aq * 16), hb + (size_t)m * HID + k0 + aq * 4);
        }
        #pragma unroll
        for (int j = 0; j < 4; j++) {
            int k = bk + j * 8;
            cp16(buf + 16384 + k * 544 + bq * 16, w2b + (size_t)(k0 + k) * DIM + bq * 4);
        }
    };

    float acc[4][4][4];
    #pragma unroll
    for (int i = 0; i < 4; i++)
        #pragma unroll
        for (int j = 0; j < 4; j++)
            #pragma unroll
            for (int k = 0; k < 4; k++) acc[i][j][k] = 0.f;

    issue(0); CP_COMMIT();
    issue(1); CP_COMMIT();

    const int kb = lane & 3, nq = lane >> 2;
    const int NS = HID / 32;   // 32
    #pragma unroll 1
    for (int s = 0; s < NS; s++) {
        CP_WAIT1();
        __syncthreads();
        const uint32_t aA = sbase + (uint32_t)(s % 3) * DN_STAGE;
        const float* Bp = (const float*)(smem + (s % 3) * DN_STAGE + 16384);
        #pragma unroll
        for (int kk = 0; kk < 4; kk++) {
            uint32_t af[4][4];
            #pragma unroll
            for (int m2 = 0; m2 < 4; m2++) {
                ldsm4(af[m2], aA + SWZ((mbase + m2 * 16 + (blk & 1) * 8 + r) * 128 + kk * 32 + (blk >> 1) * 16));
                #pragma unroll
                for (int q = 0; q < 4; q++) af[m2][q] = bits2tf32(af[m2][q]);
            }
            uint32_t b0[4], b1[4];
            #pragma unroll
            for (int p = 0; p < 4; p++) {
                int n = nbase + p * 8 + nq;
                int k = kk * 8 + kb;
                b0[p] = f2tf32(Bp[k * DN_BROW + n]);
                b1[p] = f2tf32(Bp[(k + 4) * DN_BROW + n]);
            }
            #pragma unroll
            for (int m2 = 0; m2 < 4; m2++)
                #pragma unroll
                for (int p = 0; p < 4; p++)
                    mma8(acc[m2][p], af[m2], b0[p], b1[p]);
        }
        if (s + 2 < NS) issue(s + 2);
        CP_COMMIT();
    }

    const int g = lane >> 2, t4 = lane & 3;
    float* ob = out + (size_t)(e * TPE + mt * 128) * DIM + nt * 128;
    #pragma unroll
    for (int m2 = 0; m2 < 4; m2++) {
        #pragma unroll
        for (int p = 0; p < 4; p++) {
            int row = mbase + m2 * 16 + g;
            int col = nbase + p * 8 + 2 * t4;
            float* r0 = ob + (size_t)row * DIM + col;
            float* r1 = r0 + 8 * DIM;
            *(float2*)r0 = make_float2(acc[m2][p][0], acc[m2][p][1]);
            *(float2*)r1 = make_float2(acc[m2][p][2], acc[m2][p][3]);
        }
    }
}

// ======================================================================
extern "C" void kernel_launch(void* const* d_in, const int* in_sizes, int n_in,
                              void* d_out, int out_size)
{
    (void)in_sizes; (void)n_in; (void)out_size;
    const float* x  = (const float*)d_in[0];
    const float* w1 = (const float*)d_in[1];
    const float* w2 = (const float*)d_in[2];
    const float* w3 = (const float*)d_in[3];
    float* out = (float*)d_out;

    static bool attr_set = false;
    if (!attr_set) {
        cudaFuncSetAttribute(moe_up_kernel,   cudaFuncAttributeMaxDynamicSharedMemorySize, UP_SMEM);
        cudaFuncSetAttribute(moe_down_kernel, cudaFuncAttributeMaxDynamicSharedMemorySize, DN_SMEM);
        attr_set = true;
    }

    moe_up_kernel<<<NEXP * 32, 256, UP_SMEM>>>(x, w1, w3);
    moe_down_kernel<<<NEXP * 32, 256, DN_SMEM>>>(w2, out);
}